// round 12
// baseline (speedup 1.0000x reference)
#include <cuda_runtime.h>
#include <cuda_fp16.h>
#include <cstdint>

// Problem constants
#define BB 2
#define SS 2048
#define DM 2048
#define NH 32
#define NKV 8
#define HD 64

#define LOG2E 1.4426950408889634f
#define NQKV (NH * HD + 2 * NKV * HD)   // 3072 concatenated output cols

// ---------------------------------------------------------------------------
// Scratch (allocation-free rule: __device__ globals)
// ---------------------------------------------------------------------------
__device__ __align__(1024) __half g_xh[(size_t)BB * SS * DM];
__device__ __align__(1024) __half g_wqkvT[(size_t)NQKV * DM];  // [3072, 2048]
__device__ __align__(1024) __half g_woT[(size_t)DM * DM];
__device__ __align__(1024) __half g_q[(size_t)BB * SS * NH * HD];
__device__ __align__(1024) __half g_k[(size_t)BB * SS * NKV * HD];
__device__ __align__(1024) __half g_att[(size_t)BB * SS * NH * HD];
__device__ __align__(1024) uint32_t g_vp[(size_t)BB * NKV * (SS / 2) * HD];

// ---------------------------------------------------------------------------
// Helpers
// ---------------------------------------------------------------------------
__device__ __forceinline__ uint32_t smem_u32(const void* p) {
    uint32_t a;
    asm("{ .reg .u64 t; cvta.to.shared.u64 t, %1; cvt.u32.u64 %0, t; }" : "=r"(a) : "l"(p));
    return a;
}
// pack two fp32 -> f16x2 (lo, hi) with round-to-nearest-even
__device__ __forceinline__ uint32_t h2pack(float lo, float hi) {
    uint32_t d;
    asm("cvt.rn.f16x2.f32 %0, %1, %2;" : "=r"(d) : "f"(hi), "f"(lo));
    return d;
}
__device__ __forceinline__ void cp_async16(uint32_t smem, const void* gmem) {
    asm volatile("cp.async.cg.shared.global [%0], [%1], 16;" :: "r"(smem), "l"(gmem));
}
#define CP_COMMIT() asm volatile("cp.async.commit_group;" ::: "memory")
#define CP_WAIT(n)  asm volatile("cp.async.wait_group %0;" :: "n"(n) : "memory")

// ldmatrix x4: four 8x8 b16 matrices
__device__ __forceinline__ void ldsm_x4(uint32_t& r0, uint32_t& r1,
                                        uint32_t& r2, uint32_t& r3, uint32_t addr) {
    asm volatile("ldmatrix.sync.aligned.m8n8.x4.shared.b16 {%0,%1,%2,%3}, [%4];"
                 : "=r"(r0), "=r"(r1), "=r"(r2), "=r"(r3) : "r"(addr));
}

// m16n8k16 fp16 MMA, fp32 accumulate (sm_80+ baseline; legacy HMMA pipe)
__device__ __forceinline__ void mma16n8k16(float* d, const uint32_t* a, const uint32_t* b) {
    asm volatile(
        "mma.sync.aligned.m16n8k16.row.col.f32.f16.f16.f32 "
        "{%0,%1,%2,%3}, {%4,%5,%6,%7}, {%8,%9}, {%0,%1,%2,%3};"
        : "+f"(d[0]), "+f"(d[1]), "+f"(d[2]), "+f"(d[3])
        : "r"(a[0]), "r"(a[1]), "r"(a[2]), "r"(a[3]), "r"(b[0]), "r"(b[1]));
}

// ---------------------------------------------------------------------------
// fp16 mma.sync GEMM: C = A[M,K] @ Bt[N,K]^T (fp16, K-major), ldmatrix frags.
// BM=256, BN=128, BK=64, 256 threads / 8 warps in a 4x2 grid -> 64x64 warp
// tile (32 MMAs per 8 LDSM: doubles FLOP per smem byte vs 32x64 -> crossbar
// ceiling rises from ~44% to ~65% tensor). 3-stage cp.async ring, ONE barrier
// per k-iter, 1 block/SM (162KB smem). Epilogue modes: 0 = fp32 store to Cv;
// -1 = fused QKV (q: rope+scale, k: rope, v: packed key-pair-major to vp).
// ---------------------------------------------------------------------------
#define GLD 72                   // halves per smem row (64 + 8 pad)
#define GAH_A (256 * GLD)        // A halves per stage (18432)
#define GAH_B (128 * GLD)        // B halves per stage (9216)
#define GSTH (GAH_A + GAH_B)     // halves per stage (27648)
#define GEMM_SMEM (3 * GSTH * 2) // 165888 B

__global__ __launch_bounds__(256) void gemm_f16_kernel(
    const __half* __restrict__ A, const __half* __restrict__ Bt,
    void* __restrict__ Cv, int M, int N, int K, int mode,
    __half* __restrict__ qd, __half* __restrict__ kd, uint32_t* __restrict__ vp,
    const float* __restrict__ fcos, const float* __restrict__ fsin)
{
    extern __shared__ __half smh[];
    const int tid = threadIdx.x;
    const int wid = tid >> 5, lid = tid & 31;
    const int wm = wid & 3, wn = wid >> 2;       // 4x2 warp grid, 64x64 tiles
    const int lr = lid >> 2, lc = lid & 3;
    const int bm = blockIdx.y * 256, bn = blockIdx.x * 128;

    const uint32_t sb = smem_u32(smh);

    // ldmatrix lane base offsets (in halves)
    const uint32_t aLane = (uint32_t)((wm * 64 + (lid & 15)) * GLD + (lid >> 4) * 8);
    const uint32_t bLane = (uint32_t)((wn * 64 + (lid & 7) + ((lid >> 4) & 1) * 8) * GLD
                                      + ((lid >> 3) & 1) * 8);

    float acc[4][8][4];
#pragma unroll
    for (int mt = 0; mt < 4; mt++)
#pragma unroll
        for (int nt = 0; nt < 8; nt++)
#pragma unroll
            for (int i = 0; i < 4; i++) acc[mt][nt][i] = 0.f;

    // one stage: A 256 rows + B 128 rows, 8 x 16B chunks per 64-half row
    auto load_stage = [&](int s) {
        const int st = s % 3;
        const __half* Ab = A + (size_t)bm * K + s * 64;
        const __half* Bb = Bt + (size_t)bn * K + s * 64;
#pragma unroll
        for (int i = 0; i < 8; i++) {
            int c = tid + i * 256;
            int row = c >> 3, cc = c & 7;
            cp_async16(sb + (uint32_t)(st * GSTH + row * GLD + cc * 8) * 2,
                       Ab + (size_t)row * K + cc * 8);
        }
#pragma unroll
        for (int i = 0; i < 4; i++) {
            int c = tid + i * 256;
            int row = c >> 3, cc = c & 7;
            cp_async16(sb + (uint32_t)(st * GSTH + GAH_A + row * GLD + cc * 8) * 2,
                       Bb + (size_t)row * K + cc * 8);
        }
    };

    const int nk = K / 64;
    load_stage(0); CP_COMMIT();
    load_stage(1); CP_COMMIT();

    for (int s = 0; s < nk; s++) {
        CP_WAIT(1);
        __syncthreads();                    // stage s%3 ready; (s+2)%3 free
        if (s + 2 < nk) load_stage(s + 2);
        CP_COMMIT();                        // uniform group count
        const int st = s % 3;
        const uint32_t sa = sb + (uint32_t)(st * GSTH) * 2;
        const uint32_t sbB = sb + (uint32_t)(st * GSTH + GAH_A) * 2;
#pragma unroll
        for (int kk = 0; kk < 4; kk++) {    // four k16 steps cover BK=64
            uint32_t af[4][4], bf[8][2];
#pragma unroll
            for (int mt = 0; mt < 4; mt++)
                ldsm_x4(af[mt][0], af[mt][1], af[mt][2], af[mt][3],
                        sa + (aLane + (uint32_t)(mt * 16 * GLD + kk * 16)) * 2);
#pragma unroll
            for (int p = 0; p < 4; p++)
                ldsm_x4(bf[2 * p][0], bf[2 * p][1], bf[2 * p + 1][0], bf[2 * p + 1][1],
                        sbB + (bLane + (uint32_t)(p * 16 * GLD + kk * 16)) * 2);
#pragma unroll
            for (int mt = 0; mt < 4; mt++)
#pragma unroll
                for (int nt = 0; nt < 8; nt++)
                    mma16n8k16(acc[mt][nt], af[mt], bf[nt]);
        }
    }

    // epilogue: resolve destination segment (uniform per block)
    int emode = mode;
    int colb = bn;
    float scale = 1.0f;
    if (mode < 0) {
        if (bn < NH * HD)                 { emode = 1; colb = bn; scale = 0.125f * LOG2E; }
        else if (bn < NH * HD + NKV * HD) { emode = 2; colb = bn - NH * HD; }
        else                              { emode = 3; colb = bn - NH * HD - NKV * HD; }
    }

#pragma unroll
    for (int mt = 0; mt < 4; mt++) {
        const int r0 = bm + wm * 64 + mt * 16 + lr;
        const int s0 = r0 & (SS - 1);
        const int s1 = (r0 + 8) & (SS - 1);
#pragma unroll
        for (int nt = 0; nt < 8; nt++) {
            const int col = colb + wn * 64 + nt * 8 + lc * 2;
            float a0 = acc[mt][nt][0], a1 = acc[mt][nt][1];
            float a2 = acc[mt][nt][2], a3 = acc[mt][nt][3];
            if (emode == 0) {
                float* C = (float*)Cv;
                *(float2*)&C[(size_t)r0 * DM + col] = make_float2(a0, a1);
                *(float2*)&C[(size_t)(r0 + 8) * DM + col] = make_float2(a2, a3);
            } else if (emode == 3) {
                // fused key-pair pack: lane lid^4 holds rows r0+1 / r0+9
                uint32_t w0 = h2pack(a0, a1);
                uint32_t w1 = h2pack(a2, a3);
                uint32_t pw0 = __shfl_xor_sync(0xffffffffu, w0, 4);
                uint32_t pw1 = __shfl_xor_sync(0xffffffffu, w1, 4);
                if (!(lr & 1)) {   // even rows own the pair (r0, r0+1)
                    uint32_t lo0 = __byte_perm(w0, pw0, 0x5410);
                    uint32_t hi0 = __byte_perm(w0, pw0, 0x7632);
                    uint32_t lo1 = __byte_perm(w1, pw1, 0x5410);
                    uint32_t hi1 = __byte_perm(w1, pw1, 0x7632);
                    const int bb = r0 >> 11;
                    const int sp = (r0 & (SS - 1)) >> 1;
                    const int kvh = col >> 6, d = col & 63;
                    uint32_t* dst = vp + ((size_t)(bb * NKV + kvh) * (SS / 2) + sp) * 64 + d;
                    *(uint2*)dst = make_uint2(lo0, hi0);
                    *(uint2*)(dst + 4 * 64) = make_uint2(lo1, hi1);
                }
            } else {  // rope (a0/a1 and a2/a3 are the even/odd rotation pairs)
                const int Nd = (emode == 1) ? NH * HD : NKV * HD;
                __half* C = (emode == 1) ? qd : kd;
                const int pidx = (col & 63) >> 1;
                const float c0 = fcos[s0 * 32 + pidx], si0 = fsin[s0 * 32 + pidx];
                const float c1 = fcos[s1 * 32 + pidx], si1 = fsin[s1 * 32 + pidx];
                const float sc = (emode == 1) ? scale : 1.0f;
                *(uint32_t*)&C[(size_t)r0 * Nd + col] =
                    h2pack(sc * (a0 * c0 - a1 * si0), sc * (a0 * si0 + a1 * c0));
                *(uint32_t*)&C[(size_t)(r0 + 8) * Nd + col] =
                    h2pack(sc * (a2 * c1 - a3 * si1), sc * (a2 * si1 + a3 * c1));
            }
        }
    }
}

// ---------------------------------------------------------------------------
// Merged prepass: x -> fp16 (segment A) + 4 weight transposes (segments B-E).
// ---------------------------------------------------------------------------
__global__ __launch_bounds__(256) void prep_kernel(
    const float* __restrict__ x,
    const float* __restrict__ wq, const float* __restrict__ wk,
    const float* __restrict__ wv, const float* __restrict__ wo,
    __half* __restrict__ xh, __half* __restrict__ wqkvT, __half* __restrict__ woT)
{
    int bid = blockIdx.x;
    const int tid = threadIdx.x;

    if (bid < 8192) {   // segment A: convert x (2,097,152 float4s)
        int i = bid * 256 + tid;
        float4 v = ((const float4*)x)[i];
        uint2 o;
        o.x = h2pack(v.x, v.y);
        o.y = h2pack(v.z, v.w);
        ((uint2*)xh)[i] = o;
        return;
    }
    bid -= 8192;

    const float* src;
    __half* dst;
    int C;
    if (bid < 4096)      { src = wq; dst = wqkvT;                          C = NH * HD; }
    else if (bid < 5120) { bid -= 4096; src = wk; dst = wqkvT + (size_t)(NH * HD) * DM;            C = NKV * HD; }
    else if (bid < 6144) { bid -= 5120; src = wv; dst = wqkvT + (size_t)(NH * HD + NKV * HD) * DM; C = NKV * HD; }
    else                 { bid -= 6144; src = wo; dst = woT;               C = DM; }

    __shared__ float t[32][33];
    const int nbx = C / 32;
    const int bx = (bid % nbx) * 32;
    const int by = (bid / nbx) * 32;
    const int tx = tid & 31, ty = tid >> 5;
    const int xcol = bx + tx;
#pragma unroll
    for (int i = ty; i < 32; i += 8)
        t[i][tx] = src[(size_t)(by + i) * C + xcol];
    __syncthreads();
    const int xo = by + tx;
#pragma unroll
    for (int i = ty; i < 32; i += 8)
        dst[(size_t)(bx + i) * DM + xo] = __float2half(t[tx][i]);
}

// ---------------------------------------------------------------------------
// Flash attention (causal, GQA) via mma.sync fp16 (f32 accumulate).
// Block = 128 q-rows x head x batch; 8 warps, warp owns 16 rows.
// K frags via ldmatrix.x4; PV A-frags = f16x2 packs of the S accumulator;
// V pre-packed key-pair-major -> single-LDS32 B-frags.
// 2-stage cp.async double buffer, ONE barrier per iteration. exp2 softmax.
// ---------------------------------------------------------------------------
#define AKLD 72      // halves per K row (64 + pad)
#define AVLD 72      // words per Vp row (64 + pad)
#define KS_H (64 * AKLD)
#define VP_W (32 * AVLD)

__global__ __launch_bounds__(256, 2) void attn_kernel(
    const __half* __restrict__ Q, const __half* __restrict__ Kg,
    const uint32_t* __restrict__ Vp, __half* __restrict__ O)
{
    __shared__ __align__(16) __half Ksm[2][KS_H];
    __shared__ __align__(16) uint32_t Vsm[2][VP_W];

    const int tile = gridDim.x - 1 - blockIdx.x;   // heavy tiles first
    const int m0 = tile * 128;
    const int h = blockIdx.y;
    const int b = blockIdx.z;
    const int kvh = h >> 2;
    const int tid = threadIdx.x;
    const int w = tid >> 5, lid = tid & 31;
    const int lr = lid >> 2, lc = lid & 3;
    const int row0 = m0 + w * 16 + lr;

    const int kvs = NKV * HD;  // 512
    const __half* Kbase = Kg + (size_t)b * SS * kvs + kvh * 64;
    const uint32_t* Vpb = Vp + ((size_t)(b * NKV + kvh) * (SS / 2)) * 64;

    const uint32_t kLane = (uint32_t)(((lid & 7) + ((lid >> 4) & 1) * 8) * AKLD
                                      + ((lid >> 3) & 1) * 8);

    // Persistent Q fragments (q has 0.125*log2e folded in, fp16)
    uint32_t qa[4][4];
    {
        const __half* q0 = Q + ((size_t)(b * SS + row0) * NH + h) * HD;
        const __half* q1 = q0 + (size_t)8 * NH * HD;
#pragma unroll
        for (int kk = 0; kk < 4; kk++) {
            qa[kk][0] = *(const uint32_t*)(q0 + kk * 16 + 2 * lc);
            qa[kk][1] = *(const uint32_t*)(q1 + kk * 16 + 2 * lc);
            qa[kk][2] = *(const uint32_t*)(q0 + kk * 16 + 2 * lc + 8);
            qa[kk][3] = *(const uint32_t*)(q1 + kk * 16 + 2 * lc + 8);
        }
    }

    float oacc[8][4];
#pragma unroll
    for (int nt = 0; nt < 8; nt++)
#pragma unroll
        for (int i = 0; i < 4; i++) oacc[nt][i] = 0.f;
    float mst0 = -1e30f, mst1 = -1e30f, lst0 = 0.f, lst1 = 0.f;

    const uint32_t ks_b = smem_u32(Ksm);
    const uint32_t vs_b = smem_u32(Vsm);

    auto loadKV = [&](int n0, int st) {
#pragma unroll
        for (int i = 0; i < 2; i++) {
            int c = tid + i * 256;
            int kr = c >> 3, kc = c & 7;
            cp_async16(ks_b + (uint32_t)(st * KS_H + kr * AKLD + kc * 8) * 2,
                       Kbase + (size_t)(n0 + kr) * kvs + kc * 8);
            int vr = c >> 4, vc = c & 15;
            cp_async16(vs_b + (uint32_t)(st * VP_W + vr * AVLD + vc * 4) * 4,
                       Vpb + (size_t)(n0 / 2 + vr) * 64 + vc * 4);
        }
    };

    const int niter = m0 / 64 + 2;
    loadKV(0, 0);
    CP_COMMIT();

    for (int it = 0; it < niter; it++) {
        const int n0 = it * 64;
        const int st = it & 1;
        CP_WAIT(0);
        __syncthreads();
        if (it + 1 < niter) loadKV(n0 + 64, st ^ 1);
        CP_COMMIT();

        const uint32_t ksa = ks_b + (uint32_t)(st * KS_H) * 2;
        const uint32_t* Vs = Vsm[st];

        float s[8][4];
#pragma unroll
        for (int nt = 0; nt < 8; nt++)
#pragma unroll
            for (int i = 0; i < 4; i++) s[nt][i] = 0.f;
#pragma unroll
        for (int kk = 0; kk < 4; kk++) {
            uint32_t kb[8][2];
#pragma unroll
            for (int p = 0; p < 4; p++)
                ldsm_x4(kb[2 * p][0], kb[2 * p][1], kb[2 * p + 1][0], kb[2 * p + 1][1],
                        ksa + (kLane + (uint32_t)(p * 16 * AKLD + kk * 16)) * 2);
#pragma unroll
            for (int nt = 0; nt < 8; nt++)
                mma16n8k16(s[nt], qa[kk], kb[nt]);
        }

        if (n0 + 63 > m0 + w * 16) {
#pragma unroll
            for (int nt = 0; nt < 8; nt++) {
                const int key0 = n0 + nt * 8 + 2 * lc;
                const int key1 = key0 + 1;
                if (key0 > row0) s[nt][0] = -1e30f;
                if (key1 > row0) s[nt][1] = -1e30f;
                if (key0 > row0 + 8) s[nt][2] = -1e30f;
                if (key1 > row0 + 8) s[nt][3] = -1e30f;
            }
        }

        float mx0 = -1e30f, mx1 = -1e30f;
#pragma unroll
        for (int nt = 0; nt < 8; nt++) {
            mx0 = fmaxf(mx0, fmaxf(s[nt][0], s[nt][1]));
            mx1 = fmaxf(mx1, fmaxf(s[nt][2], s[nt][3]));
        }
        mx0 = fmaxf(mx0, __shfl_xor_sync(0xffffffffu, mx0, 1));
        mx0 = fmaxf(mx0, __shfl_xor_sync(0xffffffffu, mx0, 2));
        mx1 = fmaxf(mx1, __shfl_xor_sync(0xffffffffu, mx1, 1));
        mx1 = fmaxf(mx1, __shfl_xor_sync(0xffffffffu, mx1, 2));
        const float mn0 = fmaxf(mst0, mx0), mn1 = fmaxf(mst1, mx1);
        const float corr0 = exp2f(mst0 - mn0), corr1 = exp2f(mst1 - mn1);
        mst0 = mn0; mst1 = mn1;
        float sum0 = 0.f, sum1 = 0.f;
#pragma unroll
        for (int nt = 0; nt < 8; nt++) {
            s[nt][0] = exp2f(s[nt][0] - mn0); sum0 += s[nt][0];
            s[nt][1] = exp2f(s[nt][1] - mn0); sum0 += s[nt][1];
            s[nt][2] = exp2f(s[nt][2] - mn1); sum1 += s[nt][2];
            s[nt][3] = exp2f(s[nt][3] - mn1); sum1 += s[nt][3];
        }
        sum0 += __shfl_xor_sync(0xffffffffu, sum0, 1);
        sum0 += __shfl_xor_sync(0xffffffffu, sum0, 2);
        sum1 += __shfl_xor_sync(0xffffffffu, sum1, 1);
        sum1 += __shfl_xor_sync(0xffffffffu, sum1, 2);
        lst0 = lst0 * corr0 + sum0;
        lst1 = lst1 * corr1 + sum1;
#pragma unroll
        for (int nt = 0; nt < 8; nt++) {
            oacc[nt][0] *= corr0; oacc[nt][1] *= corr0;
            oacc[nt][2] *= corr1; oacc[nt][3] *= corr1;
        }

#pragma unroll
        for (int kk = 0; kk < 4; kk++) {
            uint32_t pa[4];
            pa[0] = h2pack(s[2 * kk][0], s[2 * kk][1]);
            pa[1] = h2pack(s[2 * kk][2], s[2 * kk][3]);
            pa[2] = h2pack(s[2 * kk + 1][0], s[2 * kk + 1][1]);
            pa[3] = h2pack(s[2 * kk + 1][2], s[2 * kk + 1][3]);
#pragma unroll
            for (int nt = 0; nt < 8; nt++) {
                uint32_t vb[2];
                const uint32_t* p = &Vs[(kk * 8 + lc) * AVLD + nt * 8 + lr];
                vb[0] = p[0];
                vb[1] = p[4 * AVLD];
                mma16n8k16(oacc[nt], pa, vb);
            }
        }
    }

    const float inv0 = 1.f / lst0, inv1 = 1.f / lst1;
    __half* o0 = O + ((size_t)(b * SS + row0) * NH + h) * HD;
    __half* o1 = o0 + (size_t)8 * NH * HD;
#pragma unroll
    for (int nt = 0; nt < 8; nt++) {
        const int col = nt * 8 + lc * 2;
        *(uint32_t*)&o0[col] = h2pack(oacc[nt][0] * inv0, oacc[nt][1] * inv0);
        *(uint32_t*)&o1[col] = h2pack(oacc[nt][2] * inv1, oacc[nt][3] * inv1);
    }
}

// ---------------------------------------------------------------------------
// Launch. inputs: 0=x, 1=freqs_cos, 2=freqs_sin, 3=mask(unused),
//                 4=wq, 5=wk, 6=wv, 7=wo
// ---------------------------------------------------------------------------
extern "C" void kernel_launch(void* const* d_in, const int* in_sizes, int n_in,
                              void* d_out, int out_size)
{
    const float* x = (const float*)d_in[0];
    const float* fcos = (const float*)d_in[1];
    const float* fsin = (const float*)d_in[2];
    const float* wq = (const float*)d_in[4];
    const float* wk = (const float*)d_in[5];
    const float* wv = (const float*)d_in[6];
    const float* wo = (const float*)d_in[7];
    float* out = (float*)d_out;

    __half *xh, *wqkvT, *woT, *q, *k, *att;
    uint32_t* vp;
    cudaGetSymbolAddress((void**)&xh, g_xh);
    cudaGetSymbolAddress((void**)&wqkvT, g_wqkvT);
    cudaGetSymbolAddress((void**)&woT, g_woT);
    cudaGetSymbolAddress((void**)&q, g_q);
    cudaGetSymbolAddress((void**)&k, g_k);
    cudaGetSymbolAddress((void**)&att, g_att);
    cudaGetSymbolAddress((void**)&vp, g_vp);

    static bool attr_set = false;
    if (!attr_set) {
        cudaFuncSetAttribute(gemm_f16_kernel,
                             cudaFuncAttributeMaxDynamicSharedMemorySize, GEMM_SMEM);
        attr_set = true;
    }

    const int M = BB * SS;  // 4096

    // Merged prepass: x -> fp16 + all weight transposes in one launch
    prep_kernel<<<8192 + 4096 + 1024 + 1024 + 4096, 256>>>(
        x, wq, wk, wv, wo, xh, wqkvT, woT);

    // Fused QKV projection (256x128 tiles; per-block segment epilogue)
    gemm_f16_kernel<<<dim3(NQKV / 128, M / 256), 256, GEMM_SMEM>>>(
        xh, wqkvT, nullptr, M, NQKV, DM, /*mode=*/-1, q, k, vp, fcos, fsin);

    // Attention
    attn_kernel<<<dim3(SS / 128, NH, BB), 256>>>(q, k, vp, att);

    // Output projection (fp32 epilogue to d_out)
    gemm_f16_kernel<<<dim3(DM / 128, M / 256), 256, GEMM_SMEM>>>(
        att, woT, out, M, DM, DM, /*mode=*/0, nullptr, nullptr, nullptr, fcos, fsin);
}

// round 13
// speedup vs baseline: 1.0555x; 1.0555x over previous
#include <cuda_runtime.h>
#include <cuda_fp16.h>
#include <cstdint>

// Problem constants
#define BB 2
#define SS 2048
#define DM 2048
#define NH 32
#define NKV 8
#define HD 64

#define LOG2E 1.4426950408889634f
#define NQKV (NH * HD + 2 * NKV * HD)   // 3072 concatenated output cols

// ---------------------------------------------------------------------------
// Scratch (allocation-free rule: __device__ globals)
// ---------------------------------------------------------------------------
__device__ __align__(1024) __half g_xh[(size_t)BB * SS * DM];
__device__ __align__(1024) __half g_wqkvT[(size_t)NQKV * DM];  // [3072, 2048]
__device__ __align__(1024) __half g_woT[(size_t)DM * DM];
__device__ __align__(1024) __half g_q[(size_t)BB * SS * NH * HD];
__device__ __align__(1024) __half g_k[(size_t)BB * SS * NKV * HD];
__device__ __align__(1024) __half g_att[(size_t)BB * SS * NH * HD];
__device__ __align__(1024) uint32_t g_vp[(size_t)BB * NKV * (SS / 2) * HD];

// ---------------------------------------------------------------------------
// Helpers
// ---------------------------------------------------------------------------
__device__ __forceinline__ uint32_t smem_u32(const void* p) {
    uint32_t a;
    asm("{ .reg .u64 t; cvta.to.shared.u64 t, %1; cvt.u32.u64 %0, t; }" : "=r"(a) : "l"(p));
    return a;
}
// pack two fp32 -> f16x2 (lo, hi) with round-to-nearest-even
__device__ __forceinline__ uint32_t h2pack(float lo, float hi) {
    uint32_t d;
    asm("cvt.rn.f16x2.f32 %0, %1, %2;" : "=r"(d) : "f"(hi), "f"(lo));
    return d;
}
__device__ __forceinline__ void cp_async16(uint32_t smem, const void* gmem) {
    asm volatile("cp.async.cg.shared.global [%0], [%1], 16;" :: "r"(smem), "l"(gmem));
}
#define CP_COMMIT() asm volatile("cp.async.commit_group;" ::: "memory")
#define CP_WAIT(n)  asm volatile("cp.async.wait_group %0;" :: "n"(n) : "memory")

// ldmatrix x4: four 8x8 b16 matrices
__device__ __forceinline__ void ldsm_x4(uint32_t& r0, uint32_t& r1,
                                        uint32_t& r2, uint32_t& r3, uint32_t addr) {
    asm volatile("ldmatrix.sync.aligned.m8n8.x4.shared.b16 {%0,%1,%2,%3}, [%4];"
                 : "=r"(r0), "=r"(r1), "=r"(r2), "=r"(r3) : "r"(addr));
}

// m16n8k16 fp16 MMA, fp32 accumulate (sm_80+ baseline; legacy HMMA pipe)
__device__ __forceinline__ void mma16n8k16(float* d, const uint32_t* a, const uint32_t* b) {
    asm volatile(
        "mma.sync.aligned.m16n8k16.row.col.f32.f16.f16.f32 "
        "{%0,%1,%2,%3}, {%4,%5,%6,%7}, {%8,%9}, {%0,%1,%2,%3};"
        : "+f"(d[0]), "+f"(d[1]), "+f"(d[2]), "+f"(d[3])
        : "r"(a[0]), "r"(a[1]), "r"(a[2]), "r"(a[3]), "r"(b[0]), "r"(b[1]));
}

// ---------------------------------------------------------------------------
// fp16 mma.sync GEMM (R10 champion config): C = A[M,K] @ Bt[N,K]^T.
// BM=BN=128, BK=64, 256 threads / 8 warps (warp tile 32x64), 3-stage cp.async,
// ONE barrier per 64-deep k-iter, ldmatrix frags, 2 blocks/SM.
// Epilogue modes: 0 = fp32 store to Cv; -1 = fused QKV (q: rope+scale, k: rope,
// v: fp16 packed key-pair-major direct to vp).
// ---------------------------------------------------------------------------
#define GLD 72                 // halves per smem row (64 + 8 pad)
#define GAH (128 * GLD)        // halves per operand tile (9216)
#define GSTH (2 * GAH)         // halves per stage (18432)
#define GEMM_SMEM (3 * GSTH * 2)   // 110592 B

__global__ __launch_bounds__(256, 2) void gemm_f16_kernel(
    const __half* __restrict__ A, const __half* __restrict__ Bt,
    void* __restrict__ Cv, int M, int N, int K, int mode,
    __half* __restrict__ qd, __half* __restrict__ kd, uint32_t* __restrict__ vp,
    const float* __restrict__ fcos, const float* __restrict__ fsin)
{
    extern __shared__ __half smh[];
    const int tid = threadIdx.x;
    const int wid = tid >> 5, lid = tid & 31;
    const int wm = wid & 3, wn = wid >> 2;       // 4x2 warp grid
    const int lr = lid >> 2, lc = lid & 3;
    const int bm = blockIdx.y * 128, bn = blockIdx.x * 128;

    const uint32_t sb = smem_u32(smh);

    // ldmatrix lane base offsets (in halves)
    const uint32_t aLane = (uint32_t)((wm * 32 + (lid & 15)) * GLD + (lid >> 4) * 8);
    const uint32_t bLane = (uint32_t)((wn * 64 + (lid & 7) + ((lid >> 4) & 1) * 8) * GLD
                                      + ((lid >> 3) & 1) * 8);

    float acc[2][8][4];
#pragma unroll
    for (int mt = 0; mt < 2; mt++)
#pragma unroll
        for (int nt = 0; nt < 8; nt++)
#pragma unroll
            for (int i = 0; i < 4; i++) acc[mt][nt][i] = 0.f;

    // one stage = 128 rows x 64 halves per operand; 8 x 16B chunks per row
    auto load_stage = [&](int s) {
        const int st = s % 3;
        const __half* Ab = A + (size_t)bm * K + s * 64;
        const __half* Bb = Bt + (size_t)bn * K + s * 64;
#pragma unroll
        for (int i = 0; i < 4; i++) {
            int c = tid + i * 256;
            int row = c >> 3, cc = c & 7;
            cp_async16(sb + (uint32_t)(st * GSTH + row * GLD + cc * 8) * 2,
                       Ab + (size_t)row * K + cc * 8);
            cp_async16(sb + (uint32_t)(st * GSTH + GAH + row * GLD + cc * 8) * 2,
                       Bb + (size_t)row * K + cc * 8);
        }
    };

    const int nk = K / 64;
    load_stage(0); CP_COMMIT();
    load_stage(1); CP_COMMIT();

    for (int s = 0; s < nk; s++) {
        CP_WAIT(1);
        __syncthreads();                    // stage s%3 ready; stage (s+2)%3 free
        if (s + 2 < nk) load_stage(s + 2);
        CP_COMMIT();                        // uniform group count
        const int st = s % 3;
        const uint32_t sa = sb + (uint32_t)(st * GSTH) * 2;
        const uint32_t sbB = sb + (uint32_t)(st * GSTH + GAH) * 2;
#pragma unroll
        for (int kk = 0; kk < 4; kk++) {    // four k16 steps cover BK=64
            uint32_t af[2][4], bf[8][2];
#pragma unroll
            for (int mt = 0; mt < 2; mt++)
                ldsm_x4(af[mt][0], af[mt][1], af[mt][2], af[mt][3],
                        sa + (aLane + (uint32_t)(mt * 16 * GLD + kk * 16)) * 2);
#pragma unroll
            for (int p = 0; p < 4; p++)
                ldsm_x4(bf[2 * p][0], bf[2 * p][1], bf[2 * p + 1][0], bf[2 * p + 1][1],
                        sbB + (bLane + (uint32_t)(p * 16 * GLD + kk * 16)) * 2);
#pragma unroll
            for (int mt = 0; mt < 2; mt++)
#pragma unroll
                for (int nt = 0; nt < 8; nt++)
                    mma16n8k16(acc[mt][nt], af[mt], bf[nt]);
        }
    }

    // epilogue: resolve destination segment (uniform per block)
    int emode = mode;
    int colb = bn;
    float scale = 1.0f;
    if (mode < 0) {
        if (bn < NH * HD)                 { emode = 1; colb = bn; scale = 0.125f * LOG2E; }
        else if (bn < NH * HD + NKV * HD) { emode = 2; colb = bn - NH * HD; }
        else                              { emode = 3; colb = bn - NH * HD - NKV * HD; }
    }

#pragma unroll
    for (int mt = 0; mt < 2; mt++) {
        const int r0 = bm + wm * 32 + mt * 16 + lr;
        const int s0 = r0 & (SS - 1);
        const int s1 = (r0 + 8) & (SS - 1);
#pragma unroll
        for (int nt = 0; nt < 8; nt++) {
            const int col = colb + wn * 64 + nt * 8 + lc * 2;
            float a0 = acc[mt][nt][0], a1 = acc[mt][nt][1];
            float a2 = acc[mt][nt][2], a3 = acc[mt][nt][3];
            if (emode == 0) {
                float* C = (float*)Cv;
                *(float2*)&C[(size_t)r0 * DM + col] = make_float2(a0, a1);
                *(float2*)&C[(size_t)(r0 + 8) * DM + col] = make_float2(a2, a3);
            } else if (emode == 3) {
                // fused key-pair pack: lane lid^4 holds rows r0+1 / r0+9
                uint32_t w0 = h2pack(a0, a1);
                uint32_t w1 = h2pack(a2, a3);
                uint32_t pw0 = __shfl_xor_sync(0xffffffffu, w0, 4);
                uint32_t pw1 = __shfl_xor_sync(0xffffffffu, w1, 4);
                if (!(lr & 1)) {   // even rows own the pair (r0, r0+1)
                    uint32_t lo0 = __byte_perm(w0, pw0, 0x5410);
                    uint32_t hi0 = __byte_perm(w0, pw0, 0x7632);
                    uint32_t lo1 = __byte_perm(w1, pw1, 0x5410);
                    uint32_t hi1 = __byte_perm(w1, pw1, 0x7632);
                    const int bb = r0 >> 11;
                    const int sp = (r0 & (SS - 1)) >> 1;
                    const int kvh = col >> 6, d = col & 63;
                    uint32_t* dst = vp + ((size_t)(bb * NKV + kvh) * (SS / 2) + sp) * 64 + d;
                    *(uint2*)dst = make_uint2(lo0, hi0);
                    *(uint2*)(dst + 4 * 64) = make_uint2(lo1, hi1);
                }
            } else {  // rope (a0/a1 and a2/a3 are the even/odd rotation pairs)
                const int Nd = (emode == 1) ? NH * HD : NKV * HD;
                __half* C = (emode == 1) ? qd : kd;
                const int pidx = (col & 63) >> 1;
                const float c0 = fcos[s0 * 32 + pidx], si0 = fsin[s0 * 32 + pidx];
                const float c1 = fcos[s1 * 32 + pidx], si1 = fsin[s1 * 32 + pidx];
                const float sc = (emode == 1) ? scale : 1.0f;
                *(uint32_t*)&C[(size_t)r0 * Nd + col] =
                    h2pack(sc * (a0 * c0 - a1 * si0), sc * (a0 * si0 + a1 * c0));
                *(uint32_t*)&C[(size_t)(r0 + 8) * Nd + col] =
                    h2pack(sc * (a2 * c1 - a3 * si1), sc * (a2 * si1 + a3 * c1));
            }
        }
    }
}

// ---------------------------------------------------------------------------
// Merged prepass: x -> fp16 (segment A) + 4 weight transposes (segments B-E).
// ---------------------------------------------------------------------------
__global__ __launch_bounds__(256) void prep_kernel(
    const float* __restrict__ x,
    const float* __restrict__ wq, const float* __restrict__ wk,
    const float* __restrict__ wv, const float* __restrict__ wo,
    __half* __restrict__ xh, __half* __restrict__ wqkvT, __half* __restrict__ woT)
{
    int bid = blockIdx.x;
    const int tid = threadIdx.x;

    if (bid < 8192) {   // segment A: convert x (2,097,152 float4s)
        int i = bid * 256 + tid;
        float4 v = ((const float4*)x)[i];
        uint2 o;
        o.x = h2pack(v.x, v.y);
        o.y = h2pack(v.z, v.w);
        ((uint2*)xh)[i] = o;
        return;
    }
    bid -= 8192;

    const float* src;
    __half* dst;
    int C;
    if (bid < 4096)      { src = wq; dst = wqkvT;                          C = NH * HD; }
    else if (bid < 5120) { bid -= 4096; src = wk; dst = wqkvT + (size_t)(NH * HD) * DM;            C = NKV * HD; }
    else if (bid < 6144) { bid -= 5120; src = wv; dst = wqkvT + (size_t)(NH * HD + NKV * HD) * DM; C = NKV * HD; }
    else                 { bid -= 6144; src = wo; dst = woT;               C = DM; }

    __shared__ float t[32][33];
    const int nbx = C / 32;
    const int bx = (bid % nbx) * 32;
    const int by = (bid / nbx) * 32;
    const int tx = tid & 31, ty = tid >> 5;
    const int xcol = bx + tx;
#pragma unroll
    for (int i = ty; i < 32; i += 8)
        t[i][tx] = src[(size_t)(by + i) * C + xcol];
    __syncthreads();
    const int xo = by + tx;
#pragma unroll
    for (int i = ty; i < 32; i += 8)
        dst[(size_t)(bx + i) * DM + xo] = __float2half(t[tx][i]);
}

// ---------------------------------------------------------------------------
// Flash attention (causal, GQA) via mma.sync fp16 (f32 accumulate).
// Block = 128 q-rows x head x batch; 8 warps, warp owns 16 rows.
// K frags via ldmatrix.x4; PV A-frags = f16x2 packs of the S accumulator;
// V pre-packed key-pair-major -> single-LDS32 B-frags.
// 3-stage cp.async ring (2 iters of load slack, CP_WAIT(1) keeps the
// prefetch in flight), ONE barrier per iteration. exp2 softmax.
// ---------------------------------------------------------------------------
#define AKLD 72      // halves per K row (64 + pad)
#define AVLD 72      // words per Vp row (64 + pad)
#define KS_H (64 * AKLD)
#define VP_W (32 * AVLD)

__global__ __launch_bounds__(256, 2) void attn_kernel(
    const __half* __restrict__ Q, const __half* __restrict__ Kg,
    const uint32_t* __restrict__ Vp, __half* __restrict__ O)
{
    __shared__ __align__(16) __half Ksm[3][KS_H];
    __shared__ __align__(16) uint32_t Vsm[3][VP_W];

    const int tile = gridDim.x - 1 - blockIdx.x;   // heavy tiles first
    const int m0 = tile * 128;
    const int h = blockIdx.y;
    const int b = blockIdx.z;
    const int kvh = h >> 2;
    const int tid = threadIdx.x;
    const int w = tid >> 5, lid = tid & 31;
    const int lr = lid >> 2, lc = lid & 3;
    const int row0 = m0 + w * 16 + lr;

    const int kvs = NKV * HD;  // 512
    const __half* Kbase = Kg + (size_t)b * SS * kvs + kvh * 64;
    const uint32_t* Vpb = Vp + ((size_t)(b * NKV + kvh) * (SS / 2)) * 64;

    const uint32_t kLane = (uint32_t)(((lid & 7) + ((lid >> 4) & 1) * 8) * AKLD
                                      + ((lid >> 3) & 1) * 8);

    // Persistent Q fragments (q has 0.125*log2e folded in, fp16)
    uint32_t qa[4][4];
    {
        const __half* q0 = Q + ((size_t)(b * SS + row0) * NH + h) * HD;
        const __half* q1 = q0 + (size_t)8 * NH * HD;
#pragma unroll
        for (int kk = 0; kk < 4; kk++) {
            qa[kk][0] = *(const uint32_t*)(q0 + kk * 16 + 2 * lc);
            qa[kk][1] = *(const uint32_t*)(q1 + kk * 16 + 2 * lc);
            qa[kk][2] = *(const uint32_t*)(q0 + kk * 16 + 2 * lc + 8);
            qa[kk][3] = *(const uint32_t*)(q1 + kk * 16 + 2 * lc + 8);
        }
    }

    float oacc[8][4];
#pragma unroll
    for (int nt = 0; nt < 8; nt++)
#pragma unroll
        for (int i = 0; i < 4; i++) oacc[nt][i] = 0.f;
    float mst0 = -1e30f, mst1 = -1e30f, lst0 = 0.f, lst1 = 0.f;

    const uint32_t ks_b = smem_u32(Ksm);
    const uint32_t vs_b = smem_u32(Vsm);

    auto loadKV = [&](int n0, int st) {
#pragma unroll
        for (int i = 0; i < 2; i++) {
            int c = tid + i * 256;
            int kr = c >> 3, kc = c & 7;
            cp_async16(ks_b + (uint32_t)(st * KS_H + kr * AKLD + kc * 8) * 2,
                       Kbase + (size_t)(n0 + kr) * kvs + kc * 8);
            int vr = c >> 4, vc = c & 15;
            cp_async16(vs_b + (uint32_t)(st * VP_W + vr * AVLD + vc * 4) * 4,
                       Vpb + (size_t)(n0 / 2 + vr) * 64 + vc * 4);
        }
    };

    const int niter = m0 / 64 + 2;
    loadKV(0, 0);
    CP_COMMIT();
    if (niter > 1) loadKV(64, 1);
    CP_COMMIT();

    for (int it = 0; it < niter; it++) {
        const int n0 = it * 64;
        const int st = it % 3;
        CP_WAIT(1);
        __syncthreads();                 // stage it ready; stage (it+2)%3 free
        if (it + 2 < niter) loadKV(n0 + 128, (it + 2) % 3);
        CP_COMMIT();

        const uint32_t ksa = ks_b + (uint32_t)(st * KS_H) * 2;
        const uint32_t* Vs = Vsm[st];

        float s[8][4];
#pragma unroll
        for (int nt = 0; nt < 8; nt++)
#pragma unroll
            for (int i = 0; i < 4; i++) s[nt][i] = 0.f;
#pragma unroll
        for (int kk = 0; kk < 4; kk++) {
            uint32_t kb[8][2];
#pragma unroll
            for (int p = 0; p < 4; p++)
                ldsm_x4(kb[2 * p][0], kb[2 * p][1], kb[2 * p + 1][0], kb[2 * p + 1][1],
                        ksa + (kLane + (uint32_t)(p * 16 * AKLD + kk * 16)) * 2);
#pragma unroll
            for (int nt = 0; nt < 8; nt++)
                mma16n8k16(s[nt], qa[kk], kb[nt]);
        }

        if (n0 + 63 > m0 + w * 16) {
#pragma unroll
            for (int nt = 0; nt < 8; nt++) {
                const int key0 = n0 + nt * 8 + 2 * lc;
                const int key1 = key0 + 1;
                if (key0 > row0) s[nt][0] = -1e30f;
                if (key1 > row0) s[nt][1] = -1e30f;
                if (key0 > row0 + 8) s[nt][2] = -1e30f;
                if (key1 > row0 + 8) s[nt][3] = -1e30f;
            }
        }

        float mx0 = -1e30f, mx1 = -1e30f;
#pragma unroll
        for (int nt = 0; nt < 8; nt++) {
            mx0 = fmaxf(mx0, fmaxf(s[nt][0], s[nt][1]));
            mx1 = fmaxf(mx1, fmaxf(s[nt][2], s[nt][3]));
        }
        mx0 = fmaxf(mx0, __shfl_xor_sync(0xffffffffu, mx0, 1));
        mx0 = fmaxf(mx0, __shfl_xor_sync(0xffffffffu, mx0, 2));
        mx1 = fmaxf(mx1, __shfl_xor_sync(0xffffffffu, mx1, 1));
        mx1 = fmaxf(mx1, __shfl_xor_sync(0xffffffffu, mx1, 2));
        const float mn0 = fmaxf(mst0, mx0), mn1 = fmaxf(mst1, mx1);
        const float corr0 = exp2f(mst0 - mn0), corr1 = exp2f(mst1 - mn1);
        mst0 = mn0; mst1 = mn1;
        float sum0 = 0.f, sum1 = 0.f;
#pragma unroll
        for (int nt = 0; nt < 8; nt++) {
            s[nt][0] = exp2f(s[nt][0] - mn0); sum0 += s[nt][0];
            s[nt][1] = exp2f(s[nt][1] - mn0); sum0 += s[nt][1];
            s[nt][2] = exp2f(s[nt][2] - mn1); sum1 += s[nt][2];
            s[nt][3] = exp2f(s[nt][3] - mn1); sum1 += s[nt][3];
        }
        sum0 += __shfl_xor_sync(0xffffffffu, sum0, 1);
        sum0 += __shfl_xor_sync(0xffffffffu, sum0, 2);
        sum1 += __shfl_xor_sync(0xffffffffu, sum1, 1);
        sum1 += __shfl_xor_sync(0xffffffffu, sum1, 2);
        lst0 = lst0 * corr0 + sum0;
        lst1 = lst1 * corr1 + sum1;
#pragma unroll
        for (int nt = 0; nt < 8; nt++) {
            oacc[nt][0] *= corr0; oacc[nt][1] *= corr0;
            oacc[nt][2] *= corr1; oacc[nt][3] *= corr1;
        }

#pragma unroll
        for (int kk = 0; kk < 4; kk++) {
            uint32_t pa[4];
            pa[0] = h2pack(s[2 * kk][0], s[2 * kk][1]);
            pa[1] = h2pack(s[2 * kk][2], s[2 * kk][3]);
            pa[2] = h2pack(s[2 * kk + 1][0], s[2 * kk + 1][1]);
            pa[3] = h2pack(s[2 * kk + 1][2], s[2 * kk + 1][3]);
#pragma unroll
            for (int nt = 0; nt < 8; nt++) {
                uint32_t vb[2];
                const uint32_t* p = &Vs[(kk * 8 + lc) * AVLD + nt * 8 + lr];
                vb[0] = p[0];
                vb[1] = p[4 * AVLD];
                mma16n8k16(oacc[nt], pa, vb);
            }
        }
    }

    const float inv0 = 1.f / lst0, inv1 = 1.f / lst1;
    __half* o0 = O + ((size_t)(b * SS + row0) * NH + h) * HD;
    __half* o1 = o0 + (size_t)8 * NH * HD;
#pragma unroll
    for (int nt = 0; nt < 8; nt++) {
        const int col = nt * 8 + lc * 2;
        *(uint32_t*)&o0[col] = h2pack(oacc[nt][0] * inv0, oacc[nt][1] * inv0);
        *(uint32_t*)&o1[col] = h2pack(oacc[nt][2] * inv1, oacc[nt][3] * inv1);
    }
}

// ---------------------------------------------------------------------------
// Launch. inputs: 0=x, 1=freqs_cos, 2=freqs_sin, 3=mask(unused),
//                 4=wq, 5=wk, 6=wv, 7=wo
// ---------------------------------------------------------------------------
extern "C" void kernel_launch(void* const* d_in, const int* in_sizes, int n_in,
                              void* d_out, int out_size)
{
    const float* x = (const float*)d_in[0];
    const float* fcos = (const float*)d_in[1];
    const float* fsin = (const float*)d_in[2];
    const float* wq = (const float*)d_in[4];
    const float* wk = (const float*)d_in[5];
    const float* wv = (const float*)d_in[6];
    const float* wo = (const float*)d_in[7];
    float* out = (float*)d_out;

    __half *xh, *wqkvT, *woT, *q, *k, *att;
    uint32_t* vp;
    cudaGetSymbolAddress((void**)&xh, g_xh);
    cudaGetSymbolAddress((void**)&wqkvT, g_wqkvT);
    cudaGetSymbolAddress((void**)&woT, g_woT);
    cudaGetSymbolAddress((void**)&q, g_q);
    cudaGetSymbolAddress((void**)&k, g_k);
    cudaGetSymbolAddress((void**)&att, g_att);
    cudaGetSymbolAddress((void**)&vp, g_vp);

    static bool attr_set = false;
    if (!attr_set) {
        cudaFuncSetAttribute(gemm_f16_kernel,
                             cudaFuncAttributeMaxDynamicSharedMemorySize, GEMM_SMEM);
        attr_set = true;
    }

    const int M = BB * SS;  // 4096

    // Merged prepass: x -> fp16 + all weight transposes in one launch
    prep_kernel<<<8192 + 4096 + 1024 + 1024 + 4096, 256>>>(
        x, wq, wk, wv, wo, xh, wqkvT, woT);

    // Fused QKV projection (R10 config; per-block segment epilogue)
    gemm_f16_kernel<<<dim3(NQKV / 128, M / 128), 256, GEMM_SMEM>>>(
        xh, wqkvT, nullptr, M, NQKV, DM, /*mode=*/-1, q, k, vp, fcos, fsin);

    // Attention (3-stage KV ring)
    attn_kernel<<<dim3(SS / 128, NH, BB), 256>>>(q, k, vp, att);

    // Output projection (fp32 epilogue to d_out)
    gemm_f16_kernel<<<dim3(DM / 128, M / 128), 256, GEMM_SMEM>>>(
        att, woT, out, M, DM, DM, /*mode=*/0, nullptr, nullptr, nullptr, fcos, fsin);
}

// round 14
// speedup vs baseline: 1.0860x; 1.0289x over previous
#include <cuda_runtime.h>
#include <cuda_fp16.h>
#include <cstdint>

// Problem constants
#define BB 2
#define SS 2048
#define DM 2048
#define NH 32
#define NKV 8
#define HD 64

#define LOG2E 1.4426950408889634f
#define NQKV (NH * HD + 2 * NKV * HD)   // 3072 concatenated output cols

// ---------------------------------------------------------------------------
// Scratch (allocation-free rule: __device__ globals)
// ---------------------------------------------------------------------------
__device__ __align__(1024) __half g_xh[(size_t)BB * SS * DM];
__device__ __align__(1024) __half g_wqkvT[(size_t)NQKV * DM];  // [3072, 2048]
__device__ __align__(1024) __half g_woT[(size_t)DM * DM];
__device__ __align__(1024) __half g_q[(size_t)BB * SS * NH * HD];
__device__ __align__(1024) __half g_k[(size_t)BB * SS * NKV * HD];
__device__ __align__(1024) __half g_att[(size_t)BB * SS * NH * HD];
__device__ __align__(1024) uint32_t g_vp[(size_t)BB * NKV * (SS / 2) * HD];

// ---------------------------------------------------------------------------
// Helpers
// ---------------------------------------------------------------------------
__device__ __forceinline__ uint32_t smem_u32(const void* p) {
    uint32_t a;
    asm("{ .reg .u64 t; cvta.to.shared.u64 t, %1; cvt.u32.u64 %0, t; }" : "=r"(a) : "l"(p));
    return a;
}
// pack two fp32 -> f16x2 (lo, hi) with round-to-nearest-even
__device__ __forceinline__ uint32_t h2pack(float lo, float hi) {
    uint32_t d;
    asm("cvt.rn.f16x2.f32 %0, %1, %2;" : "=r"(d) : "f"(hi), "f"(lo));
    return d;
}
// packed fp16 exp2 (one MUFU op for two elements)
__device__ __forceinline__ uint32_t ex2_f16x2(uint32_t x) {
    uint32_t r;
    asm("ex2.approx.f16x2 %0, %1;" : "=r"(r) : "r"(x));
    return r;
}
__device__ __forceinline__ void cp_async16(uint32_t smem, const void* gmem) {
    asm volatile("cp.async.cg.shared.global [%0], [%1], 16;" :: "r"(smem), "l"(gmem));
}
#define CP_COMMIT() asm volatile("cp.async.commit_group;" ::: "memory")
#define CP_WAIT(n)  asm volatile("cp.async.wait_group %0;" :: "n"(n) : "memory")

// ldmatrix x4: four 8x8 b16 matrices
__device__ __forceinline__ void ldsm_x4(uint32_t& r0, uint32_t& r1,
                                        uint32_t& r2, uint32_t& r3, uint32_t addr) {
    asm volatile("ldmatrix.sync.aligned.m8n8.x4.shared.b16 {%0,%1,%2,%3}, [%4];"
                 : "=r"(r0), "=r"(r1), "=r"(r2), "=r"(r3) : "r"(addr));
}

// m16n8k16 fp16 MMA, fp32 accumulate (sm_80+ baseline; legacy HMMA pipe)
__device__ __forceinline__ void mma16n8k16(float* d, const uint32_t* a, const uint32_t* b) {
    asm volatile(
        "mma.sync.aligned.m16n8k16.row.col.f32.f16.f16.f32 "
        "{%0,%1,%2,%3}, {%4,%5,%6,%7}, {%8,%9}, {%0,%1,%2,%3};"
        : "+f"(d[0]), "+f"(d[1]), "+f"(d[2]), "+f"(d[3])
        : "r"(a[0]), "r"(a[1]), "r"(a[2]), "r"(a[3]), "r"(b[0]), "r"(b[1]));
}

// ---------------------------------------------------------------------------
// fp16 mma.sync GEMM (R10 champion config): C = A[M,K] @ Bt[N,K]^T.
// BM=BN=128, BK=64, 256 threads / 8 warps (warp tile 32x64), 3-stage cp.async,
// ONE barrier per 64-deep k-iter, ldmatrix frags, 2 blocks/SM.
// Epilogue modes: 0 = fp32 store to Cv; -1 = fused QKV (q: rope+scale, k: rope,
// v: fp16 packed key-pair-major direct to vp).
// ---------------------------------------------------------------------------
#define GLD 72                 // halves per smem row (64 + 8 pad)
#define GAH (128 * GLD)        // halves per operand tile (9216)
#define GSTH (2 * GAH)         // halves per stage (18432)
#define GEMM_SMEM (3 * GSTH * 2)   // 110592 B

__global__ __launch_bounds__(256, 2) void gemm_f16_kernel(
    const __half* __restrict__ A, const __half* __restrict__ Bt,
    void* __restrict__ Cv, int M, int N, int K, int mode,
    __half* __restrict__ qd, __half* __restrict__ kd, uint32_t* __restrict__ vp,
    const float* __restrict__ fcos, const float* __restrict__ fsin)
{
    extern __shared__ __half smh[];
    const int tid = threadIdx.x;
    const int wid = tid >> 5, lid = tid & 31;
    const int wm = wid & 3, wn = wid >> 2;       // 4x2 warp grid
    const int lr = lid >> 2, lc = lid & 3;
    const int bm = blockIdx.y * 128, bn = blockIdx.x * 128;

    const uint32_t sb = smem_u32(smh);

    // ldmatrix lane base offsets (in halves)
    const uint32_t aLane = (uint32_t)((wm * 32 + (lid & 15)) * GLD + (lid >> 4) * 8);
    const uint32_t bLane = (uint32_t)((wn * 64 + (lid & 7) + ((lid >> 4) & 1) * 8) * GLD
                                      + ((lid >> 3) & 1) * 8);

    float acc[2][8][4];
#pragma unroll
    for (int mt = 0; mt < 2; mt++)
#pragma unroll
        for (int nt = 0; nt < 8; nt++)
#pragma unroll
            for (int i = 0; i < 4; i++) acc[mt][nt][i] = 0.f;

    // one stage = 128 rows x 64 halves per operand; 8 x 16B chunks per row
    auto load_stage = [&](int s) {
        const int st = s % 3;
        const __half* Ab = A + (size_t)bm * K + s * 64;
        const __half* Bb = Bt + (size_t)bn * K + s * 64;
#pragma unroll
        for (int i = 0; i < 4; i++) {
            int c = tid + i * 256;
            int row = c >> 3, cc = c & 7;
            cp_async16(sb + (uint32_t)(st * GSTH + row * GLD + cc * 8) * 2,
                       Ab + (size_t)row * K + cc * 8);
            cp_async16(sb + (uint32_t)(st * GSTH + GAH + row * GLD + cc * 8) * 2,
                       Bb + (size_t)row * K + cc * 8);
        }
    };

    const int nk = K / 64;
    load_stage(0); CP_COMMIT();
    load_stage(1); CP_COMMIT();

    for (int s = 0; s < nk; s++) {
        CP_WAIT(1);
        __syncthreads();                    // stage s%3 ready; stage (s+2)%3 free
        if (s + 2 < nk) load_stage(s + 2);
        CP_COMMIT();                        // uniform group count
        const int st = s % 3;
        const uint32_t sa = sb + (uint32_t)(st * GSTH) * 2;
        const uint32_t sbB = sb + (uint32_t)(st * GSTH + GAH) * 2;
#pragma unroll
        for (int kk = 0; kk < 4; kk++) {    // four k16 steps cover BK=64
            uint32_t af[2][4], bf[8][2];
#pragma unroll
            for (int mt = 0; mt < 2; mt++)
                ldsm_x4(af[mt][0], af[mt][1], af[mt][2], af[mt][3],
                        sa + (aLane + (uint32_t)(mt * 16 * GLD + kk * 16)) * 2);
#pragma unroll
            for (int p = 0; p < 4; p++)
                ldsm_x4(bf[2 * p][0], bf[2 * p][1], bf[2 * p + 1][0], bf[2 * p + 1][1],
                        sbB + (bLane + (uint32_t)(p * 16 * GLD + kk * 16)) * 2);
#pragma unroll
            for (int mt = 0; mt < 2; mt++)
#pragma unroll
                for (int nt = 0; nt < 8; nt++)
                    mma16n8k16(acc[mt][nt], af[mt], bf[nt]);
        }
    }

    // epilogue: resolve destination segment (uniform per block)
    int emode = mode;
    int colb = bn;
    float scale = 1.0f;
    if (mode < 0) {
        if (bn < NH * HD)                 { emode = 1; colb = bn; scale = 0.125f * LOG2E; }
        else if (bn < NH * HD + NKV * HD) { emode = 2; colb = bn - NH * HD; }
        else                              { emode = 3; colb = bn - NH * HD - NKV * HD; }
    }

#pragma unroll
    for (int mt = 0; mt < 2; mt++) {
        const int r0 = bm + wm * 32 + mt * 16 + lr;
        const int s0 = r0 & (SS - 1);
        const int s1 = (r0 + 8) & (SS - 1);
#pragma unroll
        for (int nt = 0; nt < 8; nt++) {
            const int col = colb + wn * 64 + nt * 8 + lc * 2;
            float a0 = acc[mt][nt][0], a1 = acc[mt][nt][1];
            float a2 = acc[mt][nt][2], a3 = acc[mt][nt][3];
            if (emode == 0) {
                float* C = (float*)Cv;
                *(float2*)&C[(size_t)r0 * DM + col] = make_float2(a0, a1);
                *(float2*)&C[(size_t)(r0 + 8) * DM + col] = make_float2(a2, a3);
            } else if (emode == 3) {
                // fused key-pair pack: lane lid^4 holds rows r0+1 / r0+9
                uint32_t w0 = h2pack(a0, a1);
                uint32_t w1 = h2pack(a2, a3);
                uint32_t pw0 = __shfl_xor_sync(0xffffffffu, w0, 4);
                uint32_t pw1 = __shfl_xor_sync(0xffffffffu, w1, 4);
                if (!(lr & 1)) {   // even rows own the pair (r0, r0+1)
                    uint32_t lo0 = __byte_perm(w0, pw0, 0x5410);
                    uint32_t hi0 = __byte_perm(w0, pw0, 0x7632);
                    uint32_t lo1 = __byte_perm(w1, pw1, 0x5410);
                    uint32_t hi1 = __byte_perm(w1, pw1, 0x7632);
                    const int bb = r0 >> 11;
                    const int sp = (r0 & (SS - 1)) >> 1;
                    const int kvh = col >> 6, d = col & 63;
                    uint32_t* dst = vp + ((size_t)(bb * NKV + kvh) * (SS / 2) + sp) * 64 + d;
                    *(uint2*)dst = make_uint2(lo0, hi0);
                    *(uint2*)(dst + 4 * 64) = make_uint2(lo1, hi1);
                }
            } else {  // rope (a0/a1 and a2/a3 are the even/odd rotation pairs)
                const int Nd = (emode == 1) ? NH * HD : NKV * HD;
                __half* C = (emode == 1) ? qd : kd;
                const int pidx = (col & 63) >> 1;
                const float c0 = fcos[s0 * 32 + pidx], si0 = fsin[s0 * 32 + pidx];
                const float c1 = fcos[s1 * 32 + pidx], si1 = fsin[s1 * 32 + pidx];
                const float sc = (emode == 1) ? scale : 1.0f;
                *(uint32_t*)&C[(size_t)r0 * Nd + col] =
                    h2pack(sc * (a0 * c0 - a1 * si0), sc * (a0 * si0 + a1 * c0));
                *(uint32_t*)&C[(size_t)(r0 + 8) * Nd + col] =
                    h2pack(sc * (a2 * c1 - a3 * si1), sc * (a2 * si1 + a3 * c1));
            }
        }
    }
}

// ---------------------------------------------------------------------------
// Merged prepass: x -> fp16 (segment A) + 4 weight transposes (segments B-E).
// ---------------------------------------------------------------------------
__global__ __launch_bounds__(256) void prep_kernel(
    const float* __restrict__ x,
    const float* __restrict__ wq, const float* __restrict__ wk,
    const float* __restrict__ wv, const float* __restrict__ wo,
    __half* __restrict__ xh, __half* __restrict__ wqkvT, __half* __restrict__ woT)
{
    int bid = blockIdx.x;
    const int tid = threadIdx.x;

    if (bid < 8192) {   // segment A: convert x (2,097,152 float4s)
        int i = bid * 256 + tid;
        float4 v = ((const float4*)x)[i];
        uint2 o;
        o.x = h2pack(v.x, v.y);
        o.y = h2pack(v.z, v.w);
        ((uint2*)xh)[i] = o;
        return;
    }
    bid -= 8192;

    const float* src;
    __half* dst;
    int C;
    if (bid < 4096)      { src = wq; dst = wqkvT;                          C = NH * HD; }
    else if (bid < 5120) { bid -= 4096; src = wk; dst = wqkvT + (size_t)(NH * HD) * DM;            C = NKV * HD; }
    else if (bid < 6144) { bid -= 5120; src = wv; dst = wqkvT + (size_t)(NH * HD + NKV * HD) * DM; C = NKV * HD; }
    else                 { bid -= 6144; src = wo; dst = woT;               C = DM; }

    __shared__ float t[32][33];
    const int nbx = C / 32;
    const int bx = (bid % nbx) * 32;
    const int by = (bid / nbx) * 32;
    const int tx = tid & 31, ty = tid >> 5;
    const int xcol = bx + tx;
#pragma unroll
    for (int i = ty; i < 32; i += 8)
        t[i][tx] = src[(size_t)(by + i) * C + xcol];
    __syncthreads();
    const int xo = by + tx;
#pragma unroll
    for (int i = ty; i < 32; i += 8)
        dst[(size_t)(bx + i) * DM + xo] = __float2half(t[tx][i]);
}

// ---------------------------------------------------------------------------
// Flash attention (causal, GQA) via mma.sync fp16 (f32 accumulate).
// Block = 128 q-rows x head x batch; 8 warps, warp owns 16 rows.
// K frags via ldmatrix.x4; P computed with ex2.approx.f16x2 (half the MUFU
// ops, output IS the PV A-fragment); row sums via MMA against a ones
// fragment (exact consistency between P and its normalizer, no shfl).
// V pre-packed key-pair-major -> single-LDS32 B-frags.
// 3-stage cp.async ring, ONE barrier per iteration. exp2 softmax domain.
// ---------------------------------------------------------------------------
#define AKLD 72      // halves per K row (64 + pad)
#define AVLD 72      // words per Vp row (64 + pad)
#define KS_H (64 * AKLD)
#define VP_W (32 * AVLD)
#define ONES2 0x3C003C00u   // f16x2 {1.0, 1.0}

__global__ __launch_bounds__(256, 2) void attn_kernel(
    const __half* __restrict__ Q, const __half* __restrict__ Kg,
    const uint32_t* __restrict__ Vp, __half* __restrict__ O)
{
    __shared__ __align__(16) __half Ksm[3][KS_H];
    __shared__ __align__(16) uint32_t Vsm[3][VP_W];

    const int tile = gridDim.x - 1 - blockIdx.x;   // heavy tiles first
    const int m0 = tile * 128;
    const int h = blockIdx.y;
    const int b = blockIdx.z;
    const int kvh = h >> 2;
    const int tid = threadIdx.x;
    const int w = tid >> 5, lid = tid & 31;
    const int lr = lid >> 2, lc = lid & 3;
    const int row0 = m0 + w * 16 + lr;

    const int kvs = NKV * HD;  // 512
    const __half* Kbase = Kg + (size_t)b * SS * kvs + kvh * 64;
    const uint32_t* Vpb = Vp + ((size_t)(b * NKV + kvh) * (SS / 2)) * 64;

    const uint32_t kLane = (uint32_t)(((lid & 7) + ((lid >> 4) & 1) * 8) * AKLD
                                      + ((lid >> 3) & 1) * 8);

    // Persistent Q fragments (q has 0.125*log2e folded in, fp16)
    uint32_t qa[4][4];
    {
        const __half* q0 = Q + ((size_t)(b * SS + row0) * NH + h) * HD;
        const __half* q1 = q0 + (size_t)8 * NH * HD;
#pragma unroll
        for (int kk = 0; kk < 4; kk++) {
            qa[kk][0] = *(const uint32_t*)(q0 + kk * 16 + 2 * lc);
            qa[kk][1] = *(const uint32_t*)(q1 + kk * 16 + 2 * lc);
            qa[kk][2] = *(const uint32_t*)(q0 + kk * 16 + 2 * lc + 8);
            qa[kk][3] = *(const uint32_t*)(q1 + kk * 16 + 2 * lc + 8);
        }
    }

    float oacc[8][4];
#pragma unroll
    for (int nt = 0; nt < 8; nt++)
#pragma unroll
        for (int i = 0; i < 4; i++) oacc[nt][i] = 0.f;
    float mst0 = -1e30f, mst1 = -1e30f, lst0 = 0.f, lst1 = 0.f;

    const uint32_t ks_b = smem_u32(Ksm);
    const uint32_t vs_b = smem_u32(Vsm);

    auto loadKV = [&](int n0, int st) {
#pragma unroll
        for (int i = 0; i < 2; i++) {
            int c = tid + i * 256;
            int kr = c >> 3, kc = c & 7;
            cp_async16(ks_b + (uint32_t)(st * KS_H + kr * AKLD + kc * 8) * 2,
                       Kbase + (size_t)(n0 + kr) * kvs + kc * 8);
            int vr = c >> 4, vc = c & 15;
            cp_async16(vs_b + (uint32_t)(st * VP_W + vr * AVLD + vc * 4) * 4,
                       Vpb + (size_t)(n0 / 2 + vr) * 64 + vc * 4);
        }
    };

    const int niter = m0 / 64 + 2;
    loadKV(0, 0);
    CP_COMMIT();
    if (niter > 1) loadKV(64, 1);
    CP_COMMIT();

    const uint32_t ones_b[2] = {ONES2, ONES2};

    for (int it = 0; it < niter; it++) {
        const int n0 = it * 64;
        const int st = it % 3;
        CP_WAIT(1);
        __syncthreads();                 // stage it ready; stage (it+2)%3 free
        if (it + 2 < niter) loadKV(n0 + 128, (it + 2) % 3);
        CP_COMMIT();

        const uint32_t ksa = ks_b + (uint32_t)(st * KS_H) * 2;
        const uint32_t* Vs = Vsm[st];

        // S = Q K^T
        float s[8][4];
#pragma unroll
        for (int nt = 0; nt < 8; nt++)
#pragma unroll
            for (int i = 0; i < 4; i++) s[nt][i] = 0.f;
#pragma unroll
        for (int kk = 0; kk < 4; kk++) {
            uint32_t kb[8][2];
#pragma unroll
            for (int p = 0; p < 4; p++)
                ldsm_x4(kb[2 * p][0], kb[2 * p][1], kb[2 * p + 1][0], kb[2 * p + 1][1],
                        ksa + (kLane + (uint32_t)(p * 16 * AKLD + kk * 16)) * 2);
#pragma unroll
            for (int nt = 0; nt < 8; nt++)
                mma16n8k16(s[nt], qa[kk], kb[nt]);
        }

        // causal mask
        if (n0 + 63 > m0 + w * 16) {
#pragma unroll
            for (int nt = 0; nt < 8; nt++) {
                const int key0 = n0 + nt * 8 + 2 * lc;
                const int key1 = key0 + 1;
                if (key0 > row0) s[nt][0] = -1e30f;
                if (key1 > row0) s[nt][1] = -1e30f;
                if (key0 > row0 + 8) s[nt][2] = -1e30f;
                if (key1 > row0 + 8) s[nt][3] = -1e30f;
            }
        }

        // row max (quad-shared)
        float mx0 = -1e30f, mx1 = -1e30f;
#pragma unroll
        for (int nt = 0; nt < 8; nt++) {
            mx0 = fmaxf(mx0, fmaxf(s[nt][0], s[nt][1]));
            mx1 = fmaxf(mx1, fmaxf(s[nt][2], s[nt][3]));
        }
        mx0 = fmaxf(mx0, __shfl_xor_sync(0xffffffffu, mx0, 1));
        mx0 = fmaxf(mx0, __shfl_xor_sync(0xffffffffu, mx0, 2));
        mx1 = fmaxf(mx1, __shfl_xor_sync(0xffffffffu, mx1, 1));
        mx1 = fmaxf(mx1, __shfl_xor_sync(0xffffffffu, mx1, 2));
        const float mn0 = fmaxf(mst0, mx0), mn1 = fmaxf(mst1, mx1);
        const float corr0 = exp2f(mst0 - mn0), corr1 = exp2f(mst1 - mn1);
        mst0 = mn0; mst1 = mn1;

        // P = exp2(S - mn) directly in packed fp16 (half the MUFU ops);
        // masked entries: -1e30 - mn -> -inf in f16 -> ex2 -> 0.
        uint32_t p16[8][2];
#pragma unroll
        for (int nt = 0; nt < 8; nt++) {
            p16[nt][0] = ex2_f16x2(h2pack(s[nt][0] - mn0, s[nt][1] - mn0));
            p16[nt][1] = ex2_f16x2(h2pack(s[nt][2] - mn1, s[nt][3] - mn1));
        }

#pragma unroll
        for (int nt = 0; nt < 8; nt++) {
            oacc[nt][0] *= corr0; oacc[nt][1] *= corr0;
            oacc[nt][2] *= corr1; oacc[nt][3] *= corr1;
        }

        // O += P V, plus l += P @ 1 (row sums via MMA: exact over the fp16 P)
        float ls[4] = {0.f, 0.f, 0.f, 0.f};
#pragma unroll
        for (int kk = 0; kk < 4; kk++) {
            uint32_t pa[4];
            pa[0] = p16[2 * kk][0];
            pa[1] = p16[2 * kk][1];
            pa[2] = p16[2 * kk + 1][0];
            pa[3] = p16[2 * kk + 1][1];
            mma16n8k16(ls, pa, ones_b);
#pragma unroll
            for (int nt = 0; nt < 8; nt++) {
                uint32_t vb[2];
                const uint32_t* p = &Vs[(kk * 8 + lc) * AVLD + nt * 8 + lr];
                vb[0] = p[0];
                vb[1] = p[4 * AVLD];
                mma16n8k16(oacc[nt], pa, vb);
            }
        }
        lst0 = lst0 * corr0 + ls[0];
        lst1 = lst1 * corr1 + ls[2];
    }

    const float inv0 = 1.f / lst0, inv1 = 1.f / lst1;
    __half* o0 = O + ((size_t)(b * SS + row0) * NH + h) * HD;
    __half* o1 = o0 + (size_t)8 * NH * HD;
#pragma unroll
    for (int nt = 0; nt < 8; nt++) {
        const int col = nt * 8 + lc * 2;
        *(uint32_t*)&o0[col] = h2pack(oacc[nt][0] * inv0, oacc[nt][1] * inv0);
        *(uint32_t*)&o1[col] = h2pack(oacc[nt][2] * inv1, oacc[nt][3] * inv1);
    }
}

// ---------------------------------------------------------------------------
// Launch. inputs: 0=x, 1=freqs_cos, 2=freqs_sin, 3=mask(unused),
//                 4=wq, 5=wk, 6=wv, 7=wo
// ---------------------------------------------------------------------------
extern "C" void kernel_launch(void* const* d_in, const int* in_sizes, int n_in,
                              void* d_out, int out_size)
{
    const float* x = (const float*)d_in[0];
    const float* fcos = (const float*)d_in[1];
    const float* fsin = (const float*)d_in[2];
    const float* wq = (const float*)d_in[4];
    const float* wk = (const float*)d_in[5];
    const float* wv = (const float*)d_in[6];
    const float* wo = (const float*)d_in[7];
    float* out = (float*)d_out;

    __half *xh, *wqkvT, *woT, *q, *k, *att;
    uint32_t* vp;
    cudaGetSymbolAddress((void**)&xh, g_xh);
    cudaGetSymbolAddress((void**)&wqkvT, g_wqkvT);
    cudaGetSymbolAddress((void**)&woT, g_woT);
    cudaGetSymbolAddress((void**)&q, g_q);
    cudaGetSymbolAddress((void**)&k, g_k);
    cudaGetSymbolAddress((void**)&att, g_att);
    cudaGetSymbolAddress((void**)&vp, g_vp);

    static bool attr_set = false;
    if (!attr_set) {
        cudaFuncSetAttribute(gemm_f16_kernel,
                             cudaFuncAttributeMaxDynamicSharedMemorySize, GEMM_SMEM);
        attr_set = true;
    }

    const int M = BB * SS;  // 4096

    // Merged prepass: x -> fp16 + all weight transposes in one launch
    prep_kernel<<<8192 + 4096 + 1024 + 1024 + 4096, 256>>>(
        x, wq, wk, wv, wo, xh, wqkvT, woT);

    // Fused QKV projection (per-block segment epilogue)
    gemm_f16_kernel<<<dim3(NQKV / 128, M / 128), 256, GEMM_SMEM>>>(
        xh, wqkvT, nullptr, M, NQKV, DM, /*mode=*/-1, q, k, vp, fcos, fsin);

    // Attention (3-stage KV ring, f16x2 exp, MMA row sums)
    attn_kernel<<<dim3(SS / 128, NH, BB), 256>>>(q, k, vp, att);

    // Output projection (fp32 epilogue to d_out)
    gemm_f16_kernel<<<dim3(DM / 128, M / 128), 256, GEMM_SMEM>>>(
        att, woT, out, M, DM, DM, /*mode=*/0, nullptr, nullptr, nullptr, fcos, fsin);
}